// round 6
// baseline (speedup 1.0000x reference)
#include <cuda_runtime.h>
#include <cuda_bf16.h>

#define N 8192
#define F 64
#define TILES 32           // sorted key tiles of 256
#define CHN 256            // scan chunks
#define CSZ 32             // ranks per chunk

// ---------------- scratch (no allocations allowed) ----------------
__device__ float g_ltg[N * F];
__device__ float g_ssrc[N];
__device__ float g_sdst[N];
__device__ float g_P[N];   // exp(s_src)
__device__ float g_p[N];   // exp(0.2 * s_src)
__device__ float g_Qs[N];  // exp(s_dst)
__device__ float g_qs[N];  // exp(0.2 * s_dst)
__device__ unsigned long long g_key[N];          // (sortable(sdst)<<32)|idx — unique
__device__ unsigned long long g_tkey[TILES][256]; // per-tile sorted keys
__device__ int   g_perm[N];                      // perm[rank] = original index
__device__ float g_sorted[N];                    // sdst ascending
__device__ double g_ctq[CHN][72];                // chunk totals (q side), col 64 = scalar
__device__ double g_ctQ[CHN][72];
__device__ double g_coq[CHN][72];                // exclusive chunk offsets
__device__ double g_coQ[CHN][72];
__device__ double g_totq[72];
__device__ double g_totQ[72];
__device__ float g_SufQ[(N + 1) * F];
__device__ float g_Preq[(N + 1) * F];
__device__ float g_SufQs[N + 1];
__device__ float g_Preqs[N + 1];

__device__ __forceinline__ unsigned int f2sort(float f) {
    unsigned int u = __float_as_uint(f);
    return (u & 0x80000000u) ? ~u : (u | 0x80000000u);
}

// ---------------- k1: ltg = graph @ W + scalars; 4 rows per thread -----------
__global__ void k1_gemm(const float* __restrict__ graph,
                        const float* __restrict__ W,
                        const float* __restrict__ a) {
    __shared__ float sW[F * F];
    __shared__ float sa[2 * F];
    int t = threadIdx.x;  // 64 threads
    for (int i = t; i < F * F; i += 64) sW[i] = W[i];
    for (int i = t; i < 2 * F; i += 64) sa[i] = a[i];
    __syncthreads();

    int fs = (t & 3) * 16;
    int row0 = blockIdx.x * 64 + (t >> 2) * 4;

    float acc[4][16];
#pragma unroll
    for (int r = 0; r < 4; r++)
#pragma unroll
        for (int f = 0; f < 16; f++) acc[r][f] = 0.f;

    const float4* gbase = reinterpret_cast<const float4*>(graph);
#pragma unroll
    for (int k4i = 0; k4i < 16; k4i++) {
        float gv[4][4];
#pragma unroll
        for (int r = 0; r < 4; r++) {
            float4 g = __ldg(&gbase[(size_t)(row0 + r) * 16 + k4i]);
            gv[r][0] = g.x; gv[r][1] = g.y; gv[r][2] = g.z; gv[r][3] = g.w;
        }
#pragma unroll
        for (int kk = 0; kk < 4; kk++) {
            const float4* wr = reinterpret_cast<const float4*>(&sW[(k4i * 4 + kk) * F + fs]);
            float4 w[4];
#pragma unroll
            for (int f4 = 0; f4 < 4; f4++) w[f4] = wr[f4];
#pragma unroll
            for (int r = 0; r < 4; r++) {
                float gk = gv[r][kk];
#pragma unroll
                for (int f4 = 0; f4 < 4; f4++) {
                    acc[r][f4 * 4 + 0] += gk * w[f4].x;
                    acc[r][f4 * 4 + 1] += gk * w[f4].y;
                    acc[r][f4 * 4 + 2] += gk * w[f4].z;
                    acc[r][f4 * 4 + 3] += gk * w[f4].w;
                }
            }
        }
    }

    float ss[4], sd[4];
#pragma unroll
    for (int r = 0; r < 4; r++) {
        float s1 = 0.f, s2 = 0.f;
#pragma unroll
        for (int f = 0; f < 16; f++) {
            s1 += acc[r][f] * sa[fs + f];
            s2 += acc[r][f] * sa[F + fs + f];
        }
        s1 += __shfl_xor_sync(0xffffffffu, s1, 1);
        s1 += __shfl_xor_sync(0xffffffffu, s1, 2);
        s2 += __shfl_xor_sync(0xffffffffu, s2, 1);
        s2 += __shfl_xor_sync(0xffffffffu, s2, 2);
        ss[r] = s1; sd[r] = s2;
    }

#pragma unroll
    for (int r = 0; r < 4; r++) {
        float4* lo = reinterpret_cast<float4*>(g_ltg + (size_t)(row0 + r) * F + fs);
#pragma unroll
        for (int f4 = 0; f4 < 4; f4++)
            lo[f4] = make_float4(acc[r][f4 * 4 + 0], acc[r][f4 * 4 + 1],
                                 acc[r][f4 * 4 + 2], acc[r][f4 * 4 + 3]);
    }

    if ((t & 3) == 0) {
#pragma unroll
        for (int r = 0; r < 4; r++) {
            int row = row0 + r;
            g_ssrc[row] = ss[r];
            g_sdst[row] = sd[r];
            g_P[row]  = expf(ss[r]);
            g_p[row]  = expf(0.2f * ss[r]);
            g_Qs[row] = expf(sd[r]);
            g_qs[row] = expf(0.2f * sd[r]);
            g_key[row] = ((unsigned long long)f2sort(sd[r]) << 32) | (unsigned int)row;
        }
    }
}

// ---------------- k2a: bitonic sort each 256-key tile ------------------------
__global__ void k2a_sort() {
    __shared__ unsigned long long s[256];
    int t = threadIdx.x;  // 256
    s[t] = g_key[blockIdx.x * 256 + t];
    __syncthreads();
#pragma unroll
    for (int k = 2; k <= 256; k <<= 1) {
#pragma unroll
        for (int j = k >> 1; j > 0; j >>= 1) {
            int p = t ^ j;
            unsigned long long av = s[t], bv = s[p];
            if (p > t) {
                bool up = ((t & k) == 0);
                if ((av > bv) == up) { s[t] = bv; s[p] = av; }
            }
            __syncthreads();
        }
    }
    g_tkey[blockIdx.x][t] = s[t];
}

// ---------------- k2b: rank via 32 tile binary searches, scatter -------------
// 9 search steps: width 256 -> ... -> 1 -> 0 (8 steps leave width 1 = ambiguous!)
__global__ void k2b_rank() {
    __shared__ unsigned long long sk[256];
    int t = threadIdx.x;  // 128
    int i = blockIdx.x * 128 + t;
    unsigned long long mykey = g_key[i];
    int rank = 0;
#pragma unroll 1
    for (int s = 0; s < TILES; s++) {
        __syncthreads();
        sk[t] = g_tkey[s][t];
        sk[t + 128] = g_tkey[s][t + 128];
        __syncthreads();
        int lo = 0, hi = 256;
#pragma unroll
        for (int st = 0; st < 9; st++) {
            if (lo < hi) {
                int mid = (lo + hi) >> 1;
                if (sk[mid] < mykey) lo = mid + 1; else hi = mid;
            }
        }
        rank += lo;
    }
    g_perm[rank] = i;
    g_sorted[rank] = g_sdst[i];
}

// ---------------- k3a: chunk totals; lanes = features, serial over k ---------
__global__ void k3a_tot() {
    int t = threadIdx.x;  // 256
    int f = t & 63;
    int chunk = blockIdx.x * 4 + (t >> 6);
    int kbase = chunk * CSZ;

    double sq = 0.0, sQ = 0.0, ssq = 0.0, ssQ = 0.0;
#pragma unroll
    for (int kk = 0; kk < CSZ; kk++) {
        int j = g_perm[kbase + kk];
        float q = g_qs[j], Q = g_Qs[j];
        float l = g_ltg[(size_t)j * F + f];
        sq += (double)(q * l);
        sQ += (double)(Q * l);
        if (f == 0) { ssq += (double)q; ssQ += (double)Q; }
    }
    g_ctq[chunk][f] = sq;
    g_ctQ[chunk][f] = sQ;
    if (f == 0) { g_ctq[chunk][64] = ssq; g_ctQ[chunk][64] = ssQ; }
}

// ---------------- paired block-wide inclusive scan (256 threads, double2) ----
__device__ __forceinline__ double2 bscan2(double2 v, double2& total) {
    __shared__ double sx[8], sy[8];
    __shared__ double stx, sty;
    __syncthreads();
    int t = threadIdx.x, lane = t & 31, wp = t >> 5;
    double x = v.x, y = v.y;
#pragma unroll
    for (int o = 1; o < 32; o <<= 1) {
        double nx = __shfl_up_sync(0xffffffffu, x, o);
        double ny = __shfl_up_sync(0xffffffffu, y, o);
        if (lane >= o) { x += nx; y += ny; }
    }
    if (lane == 31) { sx[wp] = x; sy[wp] = y; }
    __syncthreads();
    if (t == 0) {
        double rxx = 0.0, ryy = 0.0;
#pragma unroll
        for (int i2 = 0; i2 < 8; i2++) {
            double tx = sx[i2], ty = sy[i2];
            sx[i2] = rxx; sy[i2] = ryy;
            rxx += tx; ryy += ty;
        }
        stx = rxx; sty = ryy;
    }
    __syncthreads();
    total = make_double2(stx, sty);
    return make_double2(x + sx[wp], y + sy[wp]);
}

// ---------------- k3b: scan the 256 chunk totals per column ------------------
__global__ void k3b_scan() {
    int f = blockIdx.x;   // 0..64
    int t = threadIdx.x;  // 256
    double2 v = make_double2(g_ctq[t][f], g_ctQ[t][f]);
    double2 tot;
    double2 inc = bscan2(v, tot);
    g_coq[t][f] = inc.x - v.x;
    g_coQ[t][f] = inc.y - v.y;
    if (t == 255) { g_totq[f] = inc.x; g_totQ[f] = inc.y; }
}

// ---------------- k3c: serial in-chunk scan, coalesced writes ----------------
__global__ void k3c_fin() {
    int t = threadIdx.x;  // 256
    int f = t & 63;
    int chunk = blockIdx.x * 4 + (t >> 6);
    int kbase = chunk * CSZ;

    double rq = g_coq[chunk][f], rQ = g_coQ[chunk][f];
    double totQ = g_totQ[f];
    double rqs = 0.0, rQs = 0.0, totQs = 0.0;
    if (f == 0) {
        rqs = g_coq[chunk][64]; rQs = g_coQ[chunk][64]; totQs = g_totQ[64];
    }

#pragma unroll
    for (int kk = 0; kk < CSZ; kk++) {
        int k = kbase + kk;
        int j = g_perm[k];
        float q = g_qs[j], Q = g_Qs[j];
        float l = g_ltg[(size_t)j * F + f];
        g_Preq[(size_t)k * F + f] = (float)rq;
        g_SufQ[(size_t)k * F + f] = (float)(totQ - rQ);
        rq += (double)(q * l);
        rQ += (double)(Q * l);
        if (f == 0) {
            g_Preqs[k] = (float)rqs;
            g_SufQs[k] = (float)(totQs - rQs);
            rqs += (double)q;
            rQs += (double)Q;
        }
    }
    if (chunk == CHN - 1) {
        g_Preq[(size_t)N * F + f] = (float)rq;
        g_SufQ[(size_t)N * F + f] = 0.f;
        if (f == 0) { g_Preqs[N] = (float)rqs; g_SufQs[N] = 0.f; }
    }
}

// ---------------- k4: binary-search rank + coalesced combine -----------------
// 14 search steps: width 8192 -> ... -> 1 -> 0 (13 leave width 1 = ambiguous)
__global__ void k4_out(float* __restrict__ out) {
    __shared__ int   sc[64];
    __shared__ float sP[64], sp[64], sZ[64];
    int t = threadIdx.x;  // 256
    int base = blockIdx.x * 64;

    if (t < 64) {
        int row = base + t;
        float target = -g_ssrc[row];
        int lo = 0, hi = N;
#pragma unroll
        for (int step = 0; step < 14; step++) {
            if (lo < hi) {
                int mid = (lo + hi) >> 1;
                if (g_sorted[mid] < target) lo = mid + 1; else hi = mid;
            }
        }
        int c = lo;
        float P = g_P[row], p = g_p[row];
        float Z = P * g_SufQs[c] + p * g_Preqs[c];
        sc[t] = c; sP[t] = P; sp[t] = p; sZ[t] = 1.0f / Z;
    }
    __syncthreads();

    int f = t & 63;
    int rsub = t >> 6;  // 0..3
#pragma unroll
    for (int it = 0; it < 16; it++) {
        int rl = it * 4 + rsub;
        int c = sc[rl];
        float val = (sP[rl] * g_SufQ[(size_t)c * F + f] +
                     sp[rl] * g_Preq[(size_t)c * F + f]) * sZ[rl];
        out[(size_t)(base + rl) * F + f] = val;
    }
}

// ---------------- launch ----------------
extern "C" void kernel_launch(void* const* d_in, const int* in_sizes, int n_in,
                              void* d_out, int out_size) {
    const float* graph = (const float*)d_in[0];
    const float* W     = (const float*)d_in[1];
    const float* a     = (const float*)d_in[2];
    float* out = (float*)d_out;

    k1_gemm<<<N / 64, 64>>>(graph, W, a);
    k2a_sort<<<TILES, 256>>>();
    k2b_rank<<<N / 128, 128>>>();
    k3a_tot<<<CHN / 4, 256>>>();
    k3b_scan<<<F + 1, 256>>>();
    k3c_fin<<<CHN / 4, 256>>>();
    k4_out<<<N / 64, 256>>>(out);
}

// round 8
// speedup vs baseline: 1.0942x; 1.0942x over previous
#include <cuda_runtime.h>
#include <cuda_bf16.h>

#define N 8192
#define F 64
#define TILES 32           // sorted key tiles of 256
#define CHN 1024           // scan chunks
#define CSZ 8              // ranks per chunk

// ---------------- scratch (no allocations allowed) ----------------
__device__ float g_ltg[N * F];
__device__ float g_ssrc[N];
__device__ float g_sdst[N];
__device__ float g_P[N];   // exp(s_src)
__device__ float g_p[N];   // exp(0.2 * s_src)
__device__ float g_Qs[N];  // exp(s_dst)
__device__ float g_qs[N];  // exp(0.2 * s_dst)
__device__ unsigned long long g_key[N];           // (sortable(sdst)<<32)|idx — unique
__device__ unsigned long long g_tkey[TILES][256]; // per-tile sorted keys
__device__ int   g_perm[N];                       // perm[rank] = original index
__device__ float g_sorted[N];                     // sdst ascending
__device__ double g_ctq[72][CHN];                 // chunk totals (q side), row 64 = scalar
__device__ double g_ctQ[72][CHN];
__device__ double g_coq[72][CHN];                 // exclusive chunk offsets
__device__ double g_coQ[72][CHN];
__device__ double g_totq[72];
__device__ double g_totQ[72];
__device__ float g_SufQ[(N + 1) * F];
__device__ float g_Preq[(N + 1) * F];
__device__ float g_SufQs[N + 1];
__device__ float g_Preqs[N + 1];

__device__ __forceinline__ unsigned int f2sort(float f) {
    unsigned int u = __float_as_uint(f);
    return (u & 0x80000000u) ? ~u : (u | 0x80000000u);
}

// ---------------- k1: ltg = graph @ W + scalars; 4 threads per row -----------
__global__ void k1_gemm(const float* __restrict__ graph,
                        const float* __restrict__ W,
                        const float* __restrict__ a) {
    __shared__ float sW[F * F];
    __shared__ float sa[2 * F];
    int t = threadIdx.x;  // 256
    for (int i = t; i < F * F; i += 256) sW[i] = W[i];
    if (t < 2 * F) sa[t] = a[t];
    __syncthreads();

    int row = blockIdx.x * 64 + (t >> 2);
    int fs = (t & 3) * 16;  // this thread's 16-feature sub-block

    float acc[16];
#pragma unroll
    for (int f = 0; f < 16; f++) acc[f] = 0.f;

    const float4* g4 = reinterpret_cast<const float4*>(graph + (size_t)row * F);
#pragma unroll
    for (int k4i = 0; k4i < F / 4; k4i++) {
        float4 g = __ldg(&g4[k4i]);
        float gv[4] = {g.x, g.y, g.z, g.w};
#pragma unroll
        for (int kk = 0; kk < 4; kk++) {
            float gk = gv[kk];
            const float4* wr = reinterpret_cast<const float4*>(&sW[(k4i * 4 + kk) * F + fs]);
#pragma unroll
            for (int f4 = 0; f4 < 4; f4++) {
                float4 w = wr[f4];
                acc[f4 * 4 + 0] += gk * w.x;
                acc[f4 * 4 + 1] += gk * w.y;
                acc[f4 * 4 + 2] += gk * w.z;
                acc[f4 * 4 + 3] += gk * w.w;
            }
        }
    }

    float ss = 0.f, sd = 0.f;
#pragma unroll
    for (int f = 0; f < 16; f++) {
        ss += acc[f] * sa[fs + f];
        sd += acc[f] * sa[F + fs + f];
    }
    ss += __shfl_xor_sync(0xffffffffu, ss, 1);
    ss += __shfl_xor_sync(0xffffffffu, ss, 2);
    sd += __shfl_xor_sync(0xffffffffu, sd, 1);
    sd += __shfl_xor_sync(0xffffffffu, sd, 2);

    float4* lo = reinterpret_cast<float4*>(g_ltg + (size_t)row * F + fs);
#pragma unroll
    for (int f4 = 0; f4 < 4; f4++)
        lo[f4] = make_float4(acc[f4 * 4 + 0], acc[f4 * 4 + 1],
                             acc[f4 * 4 + 2], acc[f4 * 4 + 3]);

    if ((t & 3) == 0) {
        g_ssrc[row] = ss;
        g_sdst[row] = sd;
        g_P[row]  = expf(ss);
        g_p[row]  = expf(0.2f * ss);
        g_Qs[row] = expf(sd);
        g_qs[row] = expf(0.2f * sd);
        g_key[row] = ((unsigned long long)f2sort(sd) << 32) | (unsigned int)row;
    }
}

// ---------------- k2a: bitonic sort each 256-key tile ------------------------
__global__ void k2a_sort() {
    __shared__ unsigned long long s[256];
    int t = threadIdx.x;  // 256
    s[t] = g_key[blockIdx.x * 256 + t];
    __syncthreads();
#pragma unroll
    for (int k = 2; k <= 256; k <<= 1) {
#pragma unroll
        for (int j = k >> 1; j > 0; j >>= 1) {
            int p = t ^ j;
            unsigned long long av = s[t], bv = s[p];
            if (p > t) {
                bool up = ((t & k) == 0);
                if ((av > bv) == up) { s[t] = bv; s[p] = av; }
            }
            __syncthreads();
        }
    }
    g_tkey[blockIdx.x][t] = s[t];
}

// ---------------- k2b: rank via 32 tile binary searches (9 steps), scatter ---
__global__ void k2b_rank() {
    __shared__ unsigned long long sk[256];
    int t = threadIdx.x;  // 128
    int i = blockIdx.x * 128 + t;
    unsigned long long mykey = g_key[i];
    int rank = 0;
#pragma unroll 1
    for (int s = 0; s < TILES; s++) {
        __syncthreads();
        sk[t] = g_tkey[s][t];
        sk[t + 128] = g_tkey[s][t + 128];
        __syncthreads();
        int lo = 0, hi = 256;
#pragma unroll
        for (int st = 0; st < 9; st++) {
            if (lo < hi) {
                int mid = (lo + hi) >> 1;
                if (sk[mid] < mykey) lo = mid + 1; else hi = mid;
            }
        }
        rank += lo;
    }
    g_perm[rank] = i;
    g_sorted[rank] = g_sdst[i];
}

// ---------------- k3a: chunk totals; lanes = features, 8 serial ranks --------
__global__ void k3a_tot() {
    int t = threadIdx.x;  // 256
    int f = t & 63;
    int chunk = blockIdx.x * 4 + (t >> 6);
    int kbase = chunk * CSZ;

    double sq = 0.0, sQ = 0.0, ssq = 0.0, ssQ = 0.0;
#pragma unroll
    for (int kk = 0; kk < CSZ; kk++) {
        int j = g_perm[kbase + kk];
        float q = g_qs[j], Q = g_Qs[j];
        float l = g_ltg[(size_t)j * F + f];
        sq += (double)(q * l);
        sQ += (double)(Q * l);
        if (f == 0) { ssq += (double)q; ssQ += (double)Q; }
    }
    g_ctq[f][chunk] = sq;
    g_ctQ[f][chunk] = sQ;
    if (f == 0) { g_ctq[64][chunk] = ssq; g_ctQ[64][chunk] = ssQ; }
}

// ---------------- k3b: scan 1024 chunk totals per column (1024 threads) ------
__global__ void k3b_scan() {
    __shared__ double sx[32], sy[32];
    int f = blockIdx.x;   // 0..64
    int t = threadIdx.x;  // 1024
    int lane = t & 31, wp = t >> 5;

    double vx = g_ctq[f][t], vy = g_ctQ[f][t];
    double x = vx, y = vy;
#pragma unroll
    for (int o = 1; o < 32; o <<= 1) {
        double nx = __shfl_up_sync(0xffffffffu, x, o);
        double ny = __shfl_up_sync(0xffffffffu, y, o);
        if (lane >= o) { x += nx; y += ny; }
    }
    if (lane == 31) { sx[wp] = x; sy[wp] = y; }
    __syncthreads();
    if (t < 32) {
        double wx = sx[t], wy = sy[t];
        double ix = wx, iy = wy;
#pragma unroll
        for (int o = 1; o < 32; o <<= 1) {
            double nx = __shfl_up_sync(0xffffffffu, ix, o);
            double ny = __shfl_up_sync(0xffffffffu, iy, o);
            if (t >= o) { ix += nx; iy += ny; }
        }
        sx[t] = ix - wx;  // exclusive warp offset
        sy[t] = iy - wy;
    }
    __syncthreads();
    double incx = x + sx[wp];
    double incy = y + sy[wp];
    g_coq[f][t] = incx - vx;  // exclusive
    g_coQ[f][t] = incy - vy;
    if (t == 1023) { g_totq[f] = incx; g_totQ[f] = incy; }
}

// ---------------- k3c: in-chunk serial scan (8), coalesced writes ------------
__global__ void k3c_fin() {
    int t = threadIdx.x;  // 256
    int f = t & 63;
    int chunk = blockIdx.x * 4 + (t >> 6);
    int kbase = chunk * CSZ;

    double rq = g_coq[f][chunk], rQ = g_coQ[f][chunk];
    double totQ = g_totQ[f];
    double rqs = 0.0, rQs = 0.0, totQs = 0.0;
    if (f == 0) {
        rqs = g_coq[64][chunk]; rQs = g_coQ[64][chunk]; totQs = g_totQ[64];
    }

#pragma unroll
    for (int kk = 0; kk < CSZ; kk++) {
        int k = kbase + kk;
        int j = g_perm[k];
        float q = g_qs[j], Q = g_Qs[j];
        float l = g_ltg[(size_t)j * F + f];
        g_Preq[(size_t)k * F + f] = (float)rq;
        g_SufQ[(size_t)k * F + f] = (float)(totQ - rQ);
        rq += (double)(q * l);
        rQ += (double)(Q * l);
        if (f == 0) {
            g_Preqs[k] = (float)rqs;
            g_SufQs[k] = (float)(totQs - rQs);
            rqs += (double)q;
            rQs += (double)Q;
        }
    }
    if (chunk == CHN - 1) {
        g_Preq[(size_t)N * F + f] = (float)rq;
        g_SufQ[(size_t)N * F + f] = 0.f;
        if (f == 0) { g_Preqs[N] = (float)rqs; g_SufQs[N] = 0.f; }
    }
}

// ---------------- k4: binary-search rank (14 steps) + coalesced combine ------
__global__ void k4_out(float* __restrict__ out) {
    __shared__ int   sc[64];
    __shared__ float sP[64], sp[64], sZ[64];
    int t = threadIdx.x;  // 256
    int base = blockIdx.x * 64;

    if (t < 64) {
        int row = base + t;
        float target = -g_ssrc[row];
        int lo = 0, hi = N;
#pragma unroll
        for (int step = 0; step < 14; step++) {
            if (lo < hi) {
                int mid = (lo + hi) >> 1;
                if (g_sorted[mid] < target) lo = mid + 1; else hi = mid;
            }
        }
        int c = lo;
        float P = g_P[row], p = g_p[row];
        float Z = P * g_SufQs[c] + p * g_Preqs[c];
        sc[t] = c; sP[t] = P; sp[t] = p; sZ[t] = 1.0f / Z;
    }
    __syncthreads();

    int f = t & 63;
    int rsub = t >> 6;  // 0..3
#pragma unroll
    for (int it = 0; it < 16; it++) {
        int rl = it * 4 + rsub;
        int c = sc[rl];
        float val = (sP[rl] * g_SufQ[(size_t)c * F + f] +
                     sp[rl] * g_Preq[(size_t)c * F + f]) * sZ[rl];
        out[(size_t)(base + rl) * F + f] = val;
    }
}

// ---------------- launch ----------------
extern "C" void kernel_launch(void* const* d_in, const int* in_sizes, int n_in,
                              void* d_out, int out_size) {
    const float* graph = (const float*)d_in[0];
    const float* W     = (const float*)d_in[1];
    const float* a     = (const float*)d_in[2];
    float* out = (float*)d_out;

    k1_gemm<<<N / 64, 256>>>(graph, W, a);
    k2a_sort<<<TILES, 256>>>();
    k2b_rank<<<N / 128, 128>>>();
    k3a_tot<<<CHN / 4, 256>>>();
    k3b_scan<<<F + 1, 1024>>>();
    k3c_fin<<<CHN / 4, 256>>>();
    k4_out<<<N / 64, 256>>>(out);
}